// round 1
// baseline (speedup 1.0000x reference)
#include <cuda_runtime.h>

#define TILE   32
#define HALO   5
#define HW     42          // TILE + 2*HALO
#define PITCH  44          // halo shared pitch (16B-aligned rows)
#define HPITCH 33          // h-pass shared pitch (skewed, conflict-free)
#define IMG    512
#define NIMG   32
#define NBLK   (NIMG * 16 * 16)   // 8192 tiles

#define C1 1.0e-4f
#define C2 9.0e-4f

__device__ float g_partial[NBLK];

__global__ __launch_bounds__(256) void ssim_tile_kernel(
    const float* __restrict__ pred,
    const float* __restrict__ target)
{
    __shared__ float w[11];
    __shared__ float sp[HW][PITCH];
    __shared__ float st[HW][PITCH];
    __shared__ float hh[5][HW][HPITCH];
    __shared__ float wsum[8];

    const int tid = threadIdx.x;

    // Gaussian window (normalized), computed once per block.
    if (tid == 0) {
        float e[11];
        float s = 0.f;
        #pragma unroll
        for (int i = 0; i < 11; i++) {
            float d = (float)(i - 5);
            e[i] = __expf(-d * d / 4.5f);   // 2*sigma^2 = 4.5
            s += e[i];
        }
        float inv = 1.f / s;
        #pragma unroll
        for (int i = 0; i < 11; i++) w[i] = e[i] * inv;
    }

    const int bx = blockIdx.x, by = blockIdx.y, bz = blockIdx.z;
    const float* __restrict__ pimg = pred   + (size_t)bz * IMG * IMG;
    const float* __restrict__ timg = target + (size_t)bz * IMG * IMG;
    const int r0 = by * TILE - HALO;
    const int c0 = bx * TILE - HALO;

    // ---- Load halo (zero-padded outside image; sigmoid applied in-bounds only) ----
    for (int i = tid; i < HW * HW; i += 256) {
        int r = i / HW;
        int c = i - r * HW;
        int gr = r0 + r;
        int gc = c0 + c;
        float pv = 0.f, tv = 0.f;
        if (gr >= 0 && gr < IMG && gc >= 0 && gc < IMG) {
            float x = pimg[gr * IMG + gc];
            pv = 1.f / (1.f + __expf(-x));
            tv = timg[gr * IMG + gc];
        }
        sp[r][c] = pv;
        st[r][c] = tv;
    }
    __syncthreads();

    // weights into registers
    float wr[11];
    #pragma unroll
    for (int i = 0; i < 11; i++) wr[i] = w[i];

    // ---- Horizontal pass: 42 rows x 8 segments of 4 output cols each ----
    for (int task = tid; task < HW * 8; task += 256) {
        int r  = task >> 3;
        int j0 = (task & 7) * 4;
        float a[15], b[15];
        #pragma unroll
        for (int i = 0; i < 15; i++) { a[i] = sp[r][j0 + i]; b[i] = st[r][j0 + i]; }
        #pragma unroll
        for (int u = 0; u < 4; u++) {
            float s1 = 0.f, s2 = 0.f, s3 = 0.f, s4 = 0.f, s5 = 0.f;
            #pragma unroll
            for (int k = 0; k < 11; k++) {
                float wk  = wr[k];
                float pa  = a[u + k];
                float pb  = b[u + k];
                float wpa = wk * pa;
                float wpb = wk * pb;
                s1 += wpa;
                s2 += wpb;
                s3 += wpa * pa;
                s4 += wpb * pb;
                s5 += wpa * pb;
            }
            hh[0][r][j0 + u] = s1;
            hh[1][r][j0 + u] = s2;
            hh[2][r][j0 + u] = s3;
            hh[3][r][j0 + u] = s4;
            hh[4][r][j0 + u] = s5;
        }
    }
    __syncthreads();

    // ---- Vertical pass + SSIM: each thread -> 1 col, 4 output rows ----
    const int j  = tid & 31;
    const int i0 = (tid >> 5) * 4;

    float acc[4][5];
    #pragma unroll
    for (int u = 0; u < 4; u++) {
        #pragma unroll
        for (int q = 0; q < 5; q++) acc[u][q] = 0.f;
    }

    #pragma unroll
    for (int k = 0; k < 15; k++) {
        float v0 = hh[0][i0 + k][j];
        float v1 = hh[1][i0 + k][j];
        float v2 = hh[2][i0 + k][j];
        float v3 = hh[3][i0 + k][j];
        float v4 = hh[4][i0 + k][j];
        #pragma unroll
        for (int u = 0; u < 4; u++) {
            const int kk = k - u;
            if (kk >= 0 && kk <= 10) {
                float wk = wr[kk];
                acc[u][0] += wk * v0;
                acc[u][1] += wk * v1;
                acc[u][2] += wk * v2;
                acc[u][3] += wk * v3;
                acc[u][4] += wk * v4;
            }
        }
    }

    float local = 0.f;
    #pragma unroll
    for (int u = 0; u < 4; u++) {
        float mu1  = acc[u][0];
        float mu2  = acc[u][1];
        float mu1s = mu1 * mu1;
        float mu2s = mu2 * mu2;
        float mu12 = mu1 * mu2;
        float sig1  = acc[u][2] - mu1s;
        float sig2  = acc[u][3] - mu2s;
        float sig12 = acc[u][4] - mu12;
        float num = (2.f * mu12 + C1) * (2.f * sig12 + C2);
        float den = (mu1s + mu2s + C1) * (sig1 + sig2 + C2);
        local += 1.f - num / den;
    }

    // ---- Block reduction -> partial ----
    #pragma unroll
    for (int off = 16; off; off >>= 1)
        local += __shfl_down_sync(0xffffffffu, local, off);
    if ((tid & 31) == 0) wsum[tid >> 5] = local;
    __syncthreads();
    if (tid < 8) {
        float v = wsum[tid];
        #pragma unroll
        for (int off = 4; off; off >>= 1)
            v += __shfl_down_sync(0xffu, v, off);
        if (tid == 0) {
            int blin = (bz * 16 + by) * 16 + bx;
            g_partial[blin] = v;
        }
    }
}

__global__ __launch_bounds__(256) void ssim_reduce_kernel(float* __restrict__ out)
{
    __shared__ float wsum[8];
    const int tid = threadIdx.x;
    float s = 0.f;
    for (int i = tid; i < NBLK; i += 256) s += g_partial[i];
    #pragma unroll
    for (int off = 16; off; off >>= 1)
        s += __shfl_down_sync(0xffffffffu, s, off);
    if ((tid & 31) == 0) wsum[tid >> 5] = s;
    __syncthreads();
    if (tid < 8) {
        float v = wsum[tid];
        #pragma unroll
        for (int off = 4; off; off >>= 1)
            v += __shfl_down_sync(0xffu, v, off);
        if (tid == 0) out[0] = v * (1.0f / 8388608.0f);  // / (32*512*512)
    }
}

extern "C" void kernel_launch(void* const* d_in, const int* in_sizes, int n_in,
                              void* d_out, int out_size)
{
    const float* pred   = (const float*)d_in[0];
    const float* target = (const float*)d_in[1];
    dim3 grid(16, 16, 32);
    ssim_tile_kernel<<<grid, 256>>>(pred, target);
    ssim_reduce_kernel<<<1, 256>>>((float*)d_out);
}

// round 2
// speedup vs baseline: 1.0270x; 1.0270x over previous
#include <cuda_runtime.h>

#define IMG    512
#define NIMG   32
#define SW     32          // strip width (output cols per block)
#define SH     256         // strip height
#define NCH    8           // chunks per strip (SH/32)
#define BROWS  42          // hh ring rows (32 new + 10 carry)
#define ICOLS  42          // input cols incl. horizontal halo
#define PITCH  45          // input shared pitch (odd -> conflict-free H-pass reads)
#define HPITCH 33          // h-pass shared pitch (skewed, conflict-free V-pass)
#define NBLK   1024        // 16 * 2 * 32

#define C1 1.0e-4f
#define C2 9.0e-4f

__device__ float        g_partial[NBLK];
__device__ unsigned int g_count = 0;

__global__ __launch_bounds__(256) void ssim_strip_kernel(
    const float* __restrict__ pred,
    const float* __restrict__ target,
    float* __restrict__ out)
{
    __shared__ float w[11];
    __shared__ float sp[BROWS][PITCH];
    __shared__ float st[BROWS][PITCH];
    __shared__ float hh[5][BROWS][HPITCH];
    __shared__ float wsum[8];
    __shared__ int   s_last;

    const int tid = threadIdx.x;

    if (tid == 0) {
        float e[11];
        float s = 0.f;
        #pragma unroll
        for (int i = 0; i < 11; i++) {
            float d = (float)(i - 5);
            e[i] = __expf(-d * d / 4.5f);   // 2*sigma^2 = 4.5
            s += e[i];
        }
        float inv = 1.f / s;
        #pragma unroll
        for (int i = 0; i < 11; i++) w[i] = e[i] * inv;
    }

    const int bx = blockIdx.x;          // col strip   0..15
    const int by = blockIdx.y;          // row strip   0..1
    const int bz = blockIdx.z;          // image       0..31
    const float* __restrict__ pimg = pred   + (size_t)bz * IMG * IMG;
    const float* __restrict__ timg = target + (size_t)bz * IMG * IMG;
    const int c0 = bx * SW;
    const int r0 = by * SH;

    float local = 0.f;
    float wr[11];

    for (int ch = 0; ch < NCH; ch++) {
        if (ch == 0) {
            // ---- load 42 input rows: buffer row b <-> global row r0-5+b ----
            for (int i = tid; i < BROWS * ICOLS; i += 256) {
                int b  = i / ICOLS;
                int cc = i - b * ICOLS;
                int gr = r0 - 5 + b;
                int gc = c0 - 5 + cc;
                float pv = 0.f, tv = 0.f;
                if (gr >= 0 && gr < IMG && gc >= 0 && gc < IMG) {
                    float x = pimg[gr * IMG + gc];
                    pv = 1.f / (1.f + __expf(-x));
                    tv = timg[gr * IMG + gc];
                }
                sp[b][cc] = pv;
                st[b][cc] = tv;
            }
        } else {
            __syncthreads();   // previous V-pass done reading hh / this-phase writers
            // ---- ring carry: hh rows 32..41 -> 0..9 (32 cols used) ----
            for (int i = tid; i < 5 * 10 * SW; i += 256) {
                int q  = i / (10 * SW);
                int t  = i - q * (10 * SW);
                int rr = t >> 5;
                int j  = t & 31;
                hh[q][rr][j] = hh[q][32 + rr][j];
            }
            // ---- load 32 new input rows into buffer rows 10..41 ----
            for (int i = tid; i < 32 * ICOLS; i += 256) {
                int b  = 10 + i / ICOLS;
                int cc = i % ICOLS;
                int gr = r0 - 5 + 32 * ch + b;
                int gc = c0 - 5 + cc;
                float pv = 0.f, tv = 0.f;
                if (gr < IMG && gc >= 0 && gc < IMG) {   // gr >= 10 always
                    float x = pimg[gr * IMG + gc];
                    pv = 1.f / (1.f + __expf(-x));
                    tv = timg[gr * IMG + gc];
                }
                sp[b][cc] = pv;
                st[b][cc] = tv;
            }
        }
        __syncthreads();

        #pragma unroll
        for (int i = 0; i < 11; i++) wr[i] = w[i];

        // ---- horizontal pass ----
        const int ntask = (ch == 0) ? BROWS * 8 : 32 * 8;
        const int rbase = (ch == 0) ? 0 : 10;
        for (int task = tid; task < ntask; task += 256) {
            int r  = rbase + (task >> 3);
            int j0 = (task & 7) * 4;
            float a[15], b[15];
            #pragma unroll
            for (int i = 0; i < 15; i++) { a[i] = sp[r][j0 + i]; b[i] = st[r][j0 + i]; }
            #pragma unroll
            for (int u = 0; u < 4; u++) {
                float s1 = 0.f, s2 = 0.f, s3 = 0.f, s4 = 0.f, s5 = 0.f;
                #pragma unroll
                for (int k = 0; k < 11; k++) {
                    float wk  = wr[k];
                    float pa  = a[u + k];
                    float pb  = b[u + k];
                    float wpa = wk * pa;
                    float wpb = wk * pb;
                    s1 += wpa;
                    s2 += wpb;
                    s3 += wpa * pa;
                    s4 += wpb * pb;
                    s5 += wpa * pb;
                }
                hh[0][r][j0 + u] = s1;
                hh[1][r][j0 + u] = s2;
                hh[2][r][j0 + u] = s3;
                hh[3][r][j0 + u] = s4;
                hh[4][r][j0 + u] = s5;
            }
        }
        __syncthreads();

        // ---- vertical pass + SSIM: thread -> 1 col, 4 output rows ----
        const int j  = tid & 31;
        const int i0 = (tid >> 5) * 4;   // output row (in chunk) base; buffer rows i0..i0+13

        float acc[4][5];
        #pragma unroll
        for (int u = 0; u < 4; u++)
            #pragma unroll
            for (int q = 0; q < 5; q++) acc[u][q] = 0.f;

        #pragma unroll
        for (int k = 0; k < 14; k++) {
            float v0 = hh[0][i0 + k][j];
            float v1 = hh[1][i0 + k][j];
            float v2 = hh[2][i0 + k][j];
            float v3 = hh[3][i0 + k][j];
            float v4 = hh[4][i0 + k][j];
            #pragma unroll
            for (int u = 0; u < 4; u++) {
                const int kk = k - u;
                if (kk >= 0 && kk <= 10) {
                    float wk = wr[kk];
                    acc[u][0] += wk * v0;
                    acc[u][1] += wk * v1;
                    acc[u][2] += wk * v2;
                    acc[u][3] += wk * v3;
                    acc[u][4] += wk * v4;
                }
            }
        }

        #pragma unroll
        for (int u = 0; u < 4; u++) {
            float mu1  = acc[u][0];
            float mu2  = acc[u][1];
            float mu1s = mu1 * mu1;
            float mu2s = mu2 * mu2;
            float mu12 = mu1 * mu2;
            float sig1  = acc[u][2] - mu1s;
            float sig2  = acc[u][3] - mu2s;
            float sig12 = acc[u][4] - mu12;
            float num = (2.f * mu12 + C1) * (2.f * sig12 + C2);
            float den = (mu1s + mu2s + C1) * (sig1 + sig2 + C2);
            local += 1.f - __fdividef(num, den);
        }
    }

    // ---- block reduction -> partial ----
    #pragma unroll
    for (int off = 16; off; off >>= 1)
        local += __shfl_down_sync(0xffffffffu, local, off);
    if ((tid & 31) == 0) wsum[tid >> 5] = local;
    __syncthreads();
    if (tid == 0) {
        float v = 0.f;
        #pragma unroll
        for (int i = 0; i < 8; i++) v += wsum[i];
        int blin = (blockIdx.z * 2 + blockIdx.y) * 16 + blockIdx.x;
        g_partial[blin] = v;
        __threadfence();
        unsigned old = atomicAdd(&g_count, 1u);
        s_last = (old == NBLK - 1) ? 1 : 0;
    }
    __syncthreads();

    // ---- last block: fixed-order final reduction (bit-deterministic) ----
    if (s_last) {
        __threadfence();
        float s = g_partial[tid] + g_partial[tid + 256]
                + g_partial[tid + 512] + g_partial[tid + 768];
        #pragma unroll
        for (int off = 16; off; off >>= 1)
            s += __shfl_down_sync(0xffffffffu, s, off);
        if ((tid & 31) == 0) wsum[tid >> 5] = s;
        __syncthreads();
        if (tid == 0) {
            float v = 0.f;
            #pragma unroll
            for (int i = 0; i < 8; i++) v += wsum[i];
            out[0] = v * (1.0f / 8388608.0f);   // / (32*512*512)
            g_count = 0;                        // reset for next replay
        }
    }
}

extern "C" void kernel_launch(void* const* d_in, const int* in_sizes, int n_in,
                              void* d_out, int out_size)
{
    const float* pred   = (const float*)d_in[0];
    const float* target = (const float*)d_in[1];
    dim3 grid(16, 2, 32);
    ssim_strip_kernel<<<grid, 256>>>(pred, target, (float*)d_out);
}

// round 5
// speedup vs baseline: 1.1536x; 1.1232x over previous
#include <cuda_runtime.h>

#define IMG    512
#define SW     32          // strip width
#define SH     256         // strip height
#define NCH    8           // chunks per strip
#define BROWS  42          // rows in ring (32 new + 10 carry)
#define ICOLS  42          // input cols incl. horizontal halo
#define PITCH  45          // input shared pitch (conflict-free)
#define HPITCH 33          // h-pass shared pitch (conflict-free)
#define NBLK   1024        // 16 * 2 * 32

#define C1 1.0e-4f
#define C2 9.0e-4f

__device__ float        g_partial[NBLK];
__device__ unsigned int g_count = 0;

__global__ __launch_bounds__(256) void ssim_strip_kernel(
    const float* __restrict__ pred,
    const float* __restrict__ target,
    float* __restrict__ out)
{
    __shared__ float w[11];
    __shared__ float sp[BROWS][PITCH];
    __shared__ float st[BROWS][PITCH];
    __shared__ float hh[5][BROWS][HPITCH];
    __shared__ float wsum[8];
    __shared__ int   s_last;

    const int tid = threadIdx.x;

    if (tid == 0) {
        float e[11];
        float s = 0.f;
        #pragma unroll
        for (int i = 0; i < 11; i++) {
            float d = (float)(i - 5);
            e[i] = __expf(-d * d / 4.5f);   // 2*sigma^2 = 4.5
            s += e[i];
        }
        float inv = 1.f / s;
        #pragma unroll
        for (int i = 0; i < 11; i++) w[i] = e[i] * inv;
    }

    const float* __restrict__ pimg = pred   + (size_t)blockIdx.z * IMG * IMG;
    const float* __restrict__ timg = target + (size_t)blockIdx.z * IMG * IMG;
    const int c0 = blockIdx.x * SW;
    const int r0 = blockIdx.y * SH;

    __syncthreads();          // weights visible
    float wr[11];
    #pragma unroll
    for (int i = 0; i < 11; i++) wr[i] = w[i];

    // V-pass thread mapping (fixed for whole kernel)
    const int vj  = tid & 31;
    const int vi0 = (tid >> 5) * 4;

    float local = 0.f;

    for (int ch = 0; ch < NCH; ch++) {
        if (ch == 0) {
            // ---- load 42 input rows: buffer row b <-> global row r0-5+b ----
            for (int i = tid; i < BROWS * ICOLS; i += 256) {
                int b  = i / ICOLS;
                int cc = i - b * ICOLS;
                int gr = r0 - 5 + b;
                int gc = c0 - 5 + cc;
                float pv = 0.f, tv = 0.f;
                if (gr >= 0 && gr < IMG && gc >= 0 && gc < IMG) {
                    float x = pimg[gr * IMG + gc];
                    pv = 1.f / (1.f + __expf(-x));
                    tv = timg[gr * IMG + gc];
                }
                sp[b][cc] = pv;
                st[b][cc] = tv;
            }
        } else {
            __syncthreads();   // V-pass of prev chunk done reading hh
            // ---- ring carry: hh rows 32..41 -> 0..9 ----
            for (int i = tid; i < 5 * 10 * SW; i += 256) {
                int q  = i / (10 * SW);
                int t  = i - q * (10 * SW);
                int rr = t >> 5;
                int j  = t & 31;
                hh[q][rr][j] = hh[q][32 + rr][j];
            }
            // ---- load 32 new input rows into buffer rows 10..41 ----
            const int grbase = r0 - 5 + 32 * ch;
            for (int i = tid; i < 32 * ICOLS; i += 256) {
                int b  = i / ICOLS;
                int cc = i - b * ICOLS;
                int gr = grbase + 10 + b;
                int gc = c0 - 5 + cc;
                float pv = 0.f, tv = 0.f;
                if (gr < IMG && gc >= 0 && gc < IMG) {
                    float x = pimg[gr * IMG + gc];
                    pv = 1.f / (1.f + __expf(-x));
                    tv = timg[gr * IMG + gc];
                }
                sp[10 + b][cc] = pv;
                st[10 + b][cc] = tv;
            }
        }
        __syncthreads();

        // ---- horizontal pass: per-element product precompute, static bounds ----
        const int ntask = (ch == 0) ? BROWS * 8 : 32 * 8;
        const int rbase = (ch == 0) ? 0 : 10;
        for (int task = tid; task < ntask; task += 256) {
            const int r  = rbase + (task >> 3);
            const int j0 = (task & 7) * 4;
            const float* __restrict__ pr = &sp[r][j0];
            const float* __restrict__ tr = &st[r][j0];

            float s0[4], s1[4], s2[4], s3[4], s4[4];
            #pragma unroll
            for (int u = 0; u < 4; u++) { s0[u]=0.f; s1[u]=0.f; s2[u]=0.f; s3[u]=0.f; s4[u]=0.f; }

            #pragma unroll
            for (int k = 0; k < 15; k++) {
                const float pa  = pr[k];
                const float pb  = tr[k];
                const float paa = pa * pa;
                const float pbb = pb * pb;
                const float pab = pa * pb;
                #pragma unroll
                for (int u = 0; u < 4; u++) {
                    if (k - u >= 0 && k - u <= 10) {      // compile-time after unroll
                        const float wk = wr[k - u];
                        s0[u] = fmaf(wk, pa,  s0[u]);
                        s1[u] = fmaf(wk, pb,  s1[u]);
                        s2[u] = fmaf(wk, paa, s2[u]);
                        s3[u] = fmaf(wk, pbb, s3[u]);
                        s4[u] = fmaf(wk, pab, s4[u]);
                    }
                }
            }
            #pragma unroll
            for (int u = 0; u < 4; u++) {
                hh[0][r][j0 + u] = s0[u];
                hh[1][r][j0 + u] = s1[u];
                hh[2][r][j0 + u] = s2[u];
                hh[3][r][j0 + u] = s3[u];
                hh[4][r][j0 + u] = s4[u];
            }
        }
        __syncthreads();

        // ---- vertical pass: field-major, register-staged, no predication ----
        float acc[5][4];
        #pragma unroll
        for (int q = 0; q < 5; q++) {
            float v[14];
            #pragma unroll
            for (int k = 0; k < 14; k++) v[k] = hh[q][vi0 + k][vj];
            #pragma unroll
            for (int u = 0; u < 4; u++) {
                float a = 0.f;
                #pragma unroll
                for (int k = 0; k < 11; k++) a = fmaf(wr[k], v[u + k], a);
                acc[q][u] = a;
            }
        }

        #pragma unroll
        for (int u = 0; u < 4; u++) {
            const float mu1  = acc[0][u];
            const float mu2  = acc[1][u];
            const float mu1s = mu1 * mu1;
            const float mu2s = mu2 * mu2;
            const float mu12 = mu1 * mu2;
            const float sig1  = acc[2][u] - mu1s;
            const float sig2  = acc[3][u] - mu2s;
            const float sig12 = acc[4][u] - mu12;
            const float num = (2.f * mu12 + C1) * (2.f * sig12 + C2);
            const float den = (mu1s + mu2s + C1) * (sig1 + sig2 + C2);
            local += 1.f - __fdividef(num, den);
        }
    }

    // ---- block reduction -> partial ----
    #pragma unroll
    for (int off = 16; off; off >>= 1)
        local += __shfl_down_sync(0xffffffffu, local, off);
    if ((tid & 31) == 0) wsum[tid >> 5] = local;
    __syncthreads();
    if (tid == 0) {
        float v = 0.f;
        #pragma unroll
        for (int i = 0; i < 8; i++) v += wsum[i];
        int blin = (blockIdx.z * 2 + blockIdx.y) * 16 + blockIdx.x;
        g_partial[blin] = v;
        __threadfence();
        unsigned old = atomicAdd(&g_count, 1u);
        s_last = (old == NBLK - 1) ? 1 : 0;
    }
    __syncthreads();

    // ---- last block: fixed-order final reduction (bit-deterministic) ----
    if (s_last) {
        __threadfence();
        float s = g_partial[tid] + g_partial[tid + 256]
                + g_partial[tid + 512] + g_partial[tid + 768];
        #pragma unroll
        for (int off = 16; off; off >>= 1)
            s += __shfl_down_sync(0xffffffffu, s, off);
        if ((tid & 31) == 0) wsum[tid >> 5] = s;
        __syncthreads();
        if (tid == 0) {
            float v = 0.f;
            #pragma unroll
            for (int i = 0; i < 8; i++) v += wsum[i];
            out[0] = v * (1.0f / 8388608.0f);   // / (32*512*512)
            g_count = 0;                        // reset for next replay
        }
    }
}

extern "C" void kernel_launch(void* const* d_in, const int* in_sizes, int n_in,
                              void* d_out, int out_size)
{
    const float* pred   = (const float*)d_in[0];
    const float* target = (const float*)d_in[1];
    dim3 grid(16, 2, 32);
    ssim_strip_kernel<<<grid, 256>>>(pred, target, (float*)d_out);
}